// round 4
// baseline (speedup 1.0000x reference)
#include <cuda_runtime.h>
#include <math.h>

#define NW   296
#define FMD  74
#define NBIN 2701        // 74*73/2
#define NHEAD 64
#define NEMB 48
#define BMAX 2048

// __device__ scratch (no allocations allowed)
__device__ float g_wA[NBIN * NHEAD];        // (wNDI[h,I,J]-wNDI[h,J,I])/16, bin-major
__device__ float g_wDIeff[FMD * NHEAD];     // (colsum-rowsum)/4, K-major
__device__ unsigned short g_binIJ[NBIN];    // (I<<8)|J
__device__ float g_P[BMAX * NBIN];          // pooled NDI (raw 16-pair sums)
__device__ float g_U[BMAX * FMD];           // group sums of x (4 per group)

__device__ __forceinline__ float elu1(float v) { return v > 0.f ? v : expm1f(v); }

// ---------------- prep: build effective weights + LUT ----------------
__global__ __launch_bounds__(256) void prep_kernel(const float* __restrict__ wDI,
                                                   const float* __restrict__ wNDI) {
    int blk = blockIdx.x;
    int tid = threadIdx.x;
    if (blk < NHEAD) {
        __shared__ float w[FMD * FMD];
        const float* src = wNDI + blk * FMD * FMD;
        for (int i = tid; i < FMD * FMD; i += blockDim.x) w[i] = src[i];
        __syncthreads();
        for (int t = tid; t < NBIN; t += blockDim.x) {
            // invert upper-triangular index: S(I) = I*73 - I*(I-1)/2
            int I = (int)((147.0f - sqrtf(147.0f * 147.0f - 8.0f * (float)t)) * 0.5f);
            I = max(0, min(72, I));
            while (I > 0 && (I * 73 - (I * (I - 1)) / 2) > t) I--;
            while (I < 72 && ((I + 1) * 73 - ((I + 1) * I) / 2) <= t) I++;
            int J = I + 1 + (t - (I * 73 - (I * (I - 1)) / 2));
            g_wA[t * NHEAD + blk] = (w[I * FMD + J] - w[J * FMD + I]) * (1.0f / 16.0f);
            if (blk == 0) g_binIJ[t] = (unsigned short)((I << 8) | J);
        }
    } else {
        int part = blk - NHEAD;  // 0..3
        for (int idx = part * blockDim.x + tid; idx < FMD * NHEAD; idx += 4 * blockDim.x) {
            int K = idx / NHEAD, h = idx % NHEAD;
            const float* src = wDI + h * FMD * FMD;
            float cs = 0.f, rs = 0.f;
            #pragma unroll 4
            for (int I = 0; I < FMD; I++) {
                cs += src[I * FMD + K];   // sum over first index (column K)
                rs += src[K * FMD + I];   // sum over second index (row K)
            }
            g_wDIeff[idx] = (cs - rs) * 0.25f;  // idx = K*NHEAD + h ; /4 folds mean
        }
    }
}

// ---------------- pool: per-row upper-triangle pooled NDI ----------------
__global__ __launch_bounds__(256) void pool_kernel(const float* __restrict__ x) {
    __shared__ __align__(16) float xe[NW];
    int row = blockIdx.x;
    int tid = threadIdx.x;
    const float* xr = x + row * 300;          // x0 = x[:, :296]
    for (int i = tid; i < NW; i += blockDim.x) xe[i] = xr[i] + 5e-6f; // eps/2 folded in
    __syncthreads();
    const float4* xs4 = (const float4*)xe;
    if (tid < FMD) {
        float4 v = xs4[tid];
        g_U[row * FMD + tid] = v.x + v.y + v.z + v.w;  // group sums (const offset cancels)
    }
    float* Pr = g_P + (size_t)row * NBIN;
    for (int bin = tid; bin < NBIN; bin += blockDim.x) {
        unsigned ij = g_binIJ[bin];
        float4 a = xs4[ij >> 8];    // x_i group (rows I)
        float4 b = xs4[ij & 255];   // x_j group (cols J)
        float av[4] = {a.x, a.y, a.z, a.w};
        float bv[4] = {b.x, b.y, b.z, b.w};
        float acc = 0.f;
        #pragma unroll
        for (int j = 0; j < 4; j++) {
            float xj = bv[j];
            #pragma unroll
            for (int i = 0; i < 4; i += 2) {
                // pair two fractions over a common denominator: 1 rcp per 2 pairs
                float s0 = av[i]     + xj, d0 = xj - av[i];
                float s1 = av[i + 1] + xj, d1 = xj - av[i + 1];
                float num = fmaf(d0, s1, d1 * s0);
                float den = s0 * s1;
                float y;
                asm("rcp.approx.f32 %0, %1;" : "=f"(y) : "f"(den));
                acc = fmaf(num, y, acc);
            }
        }
        Pr[bin] = acc;   // raw sum; /16 folded into g_wA
    }
}

// ---------------- fuse: head contraction + full MLP tail ----------------
__global__ __launch_bounds__(256) void fuse_kernel(
    const float* __restrict__ bDI,   const float* __restrict__ fcDI_w,  const float* __restrict__ fcDI_b,
    const float* __restrict__ bNDI,  const float* __restrict__ fcNDI_w, const float* __restrict__ fcNDI_b,
    const float* __restrict__ fc1_w, const float* __restrict__ fc1_b,
    const float* __restrict__ l1_w,  const float* __restrict__ l1_b,
    const float* __restrict__ l2_w,  const float* __restrict__ l2_b,
    float* __restrict__ out)
{
    const int RB = 16;
    __shared__ float ps[RB][129];      // padded: avoid same-bank across rows
    __shared__ float hN[RB][NHEAD];
    __shared__ float hD[RB][NHEAD];
    __shared__ float sus[RB][FMD];
    __shared__ float emb[RB][2 * NEMB];
    __shared__ float z1[RB][NEMB];
    __shared__ float z2[RB][20];

    int tid = threadIdx.x;
    int row0 = blockIdx.x * RB;
    int hq = tid & 15;   // head quad: heads 4*hq..4*hq+3
    int rg = tid >> 4;   // row 0..15

    float acc[4] = {0.f, 0.f, 0.f, 0.f};
    for (int c0 = 0; c0 < NBIN; c0 += 128) {
        int nb = min(128, NBIN - c0);
        for (int idx = tid; idx < RB * 128; idx += blockDim.x) {
            int r = idx >> 7, b = idx & 127;
            ps[r][b] = (b < nb) ? g_P[(size_t)(row0 + r) * NBIN + c0 + b] : 0.f;
        }
        __syncthreads();
        const float4* wp = (const float4*)(g_wA + (size_t)c0 * NHEAD) + hq;
        #pragma unroll 4
        for (int b = 0; b < nb; b++) {
            float4 w = wp[(size_t)b * 16];
            float p = ps[rg][b];
            acc[0] = fmaf(p, w.x, acc[0]);
            acc[1] = fmaf(p, w.y, acc[1]);
            acc[2] = fmaf(p, w.z, acc[2]);
            acc[3] = fmaf(p, w.w, acc[3]);
        }
        __syncthreads();
    }

    // DI head: h_DI = su . wDIeff
    for (int idx = tid; idx < RB * FMD; idx += blockDim.x)
        sus[idx / FMD][idx % FMD] = g_U[(size_t)(row0 + idx / FMD) * FMD + idx % FMD];
    __syncthreads();
    float dacc[4] = {0.f, 0.f, 0.f, 0.f};
    #pragma unroll 2
    for (int K = 0; K < FMD; K++) {
        float4 w = *(const float4*)(g_wDIeff + K * NHEAD + 4 * hq);
        float p = sus[rg][K];
        dacc[0] = fmaf(p, w.x, dacc[0]);
        dacc[1] = fmaf(p, w.y, dacc[1]);
        dacc[2] = fmaf(p, w.z, dacc[2]);
        dacc[3] = fmaf(p, w.w, dacc[3]);
    }
    #pragma unroll
    for (int k = 0; k < 4; k++) {
        hN[rg][4 * hq + k] = elu1(acc[k]  + bNDI[4 * hq + k]);
        hD[rg][4 * hq + k] = elu1(dacc[k] + bDI[4 * hq + k]);
    }
    __syncthreads();

    // eDI / eNDI (48 each) -> emb[96]
    for (int idx = tid; idx < RB * NEMB; idx += blockDim.x) {
        int r = idx / NEMB, e = idx % NEMB;
        float v = fcDI_b[e], v2 = fcNDI_b[e];
        #pragma unroll 8
        for (int h = 0; h < NHEAD; h++) {
            v  = fmaf(fcDI_w[e * NHEAD + h],  hD[r][h], v);
            v2 = fmaf(fcNDI_w[e * NHEAD + h], hN[r][h], v2);
        }
        emb[r][e]        = elu1(v);
        emb[r][NEMB + e] = elu1(v2);
    }
    __syncthreads();

    // fc1: 96 -> 48
    for (int idx = tid; idx < RB * NEMB; idx += blockDim.x) {
        int r = idx / NEMB, o = idx % NEMB;
        float v = fc1_b[o];
        #pragma unroll 8
        for (int c = 0; c < 2 * NEMB; c++) v = fmaf(fc1_w[o * 2 * NEMB + c], emb[r][c], v);
        z1[r][o] = elu1(v);
    }
    __syncthreads();

    // l1: 48 -> 20
    for (int idx = tid; idx < RB * 20; idx += blockDim.x) {
        int r = idx / 20, o = idx % 20;
        float v = l1_b[o];
        #pragma unroll 8
        for (int c = 0; c < NEMB; c++) v = fmaf(l1_w[o * NEMB + c], z1[r][c], v);
        z2[r][o] = elu1(v);
    }
    __syncthreads();

    // l2: 20 -> 1, sigmoid
    if (tid < RB) {
        float v = l2_b[0];
        #pragma unroll
        for (int c = 0; c < 20; c++) v = fmaf(l2_w[c], z2[tid][c], v);
        out[row0 + tid] = 1.0f / (1.0f + expf(-v));
    }
}

extern "C" void kernel_launch(void* const* d_in, const int* in_sizes, int n_in,
                              void* d_out, int out_size) {
    const float* x       = (const float*)d_in[0];
    const float* wDI     = (const float*)d_in[1];
    const float* bDI     = (const float*)d_in[2];
    const float* fcDI_w  = (const float*)d_in[3];
    const float* fcDI_b  = (const float*)d_in[4];
    const float* wNDI    = (const float*)d_in[5];
    const float* bNDI    = (const float*)d_in[6];
    const float* fcNDI_w = (const float*)d_in[7];
    const float* fcNDI_b = (const float*)d_in[8];
    const float* fc1_w   = (const float*)d_in[9];
    const float* fc1_b   = (const float*)d_in[10];
    const float* l1_w    = (const float*)d_in[11];
    const float* l1_b    = (const float*)d_in[12];
    const float* l2_w    = (const float*)d_in[13];
    const float* l2_b    = (const float*)d_in[14];
    float* out = (float*)d_out;

    int B = in_sizes[0] / 300;   // 2048

    prep_kernel<<<NHEAD + 4, 256>>>(wDI, wNDI);
    pool_kernel<<<B, 256>>>(x);
    fuse_kernel<<<B / 16, 256>>>(bDI, fcDI_w, fcDI_b, bNDI, fcNDI_w, fcNDI_b,
                                 fc1_w, fc1_b, l1_w, l1_b, l2_w, l2_b, out);
}

// round 5
// speedup vs baseline: 1.4561x; 1.4561x over previous
#include <cuda_runtime.h>
#include <math.h>

#define NW    296
#define FMD   74
#define NBIN  2701        // 74*73/2
#define NHEAD 64
#define NEMB  48
#define RB    16
#define SEGS  8
#define SEGLEN ((NBIN + SEGS - 1) / SEGS)   // 338

// __device__ scratch (no allocations allowed)
__device__ float g_wA[NBIN * NHEAD];        // (wNDI[h,I,J]-wNDI[h,J,I])/16, bin-major
__device__ float g_wDIeff[FMD * NHEAD];     // (colsum-rowsum)/4, K-major
__device__ unsigned short g_binIJ[NBIN];    // (I<<8)|J

__device__ __forceinline__ float elu1(float v) { return v > 0.f ? v : expm1f(v); }

__device__ __forceinline__ unsigned long long pk2(float a, float b) {
    unsigned long long r;
    asm("mov.b64 %0, {%1, %2};" : "=l"(r) : "f"(a), "f"(b));
    return r;
}
__device__ __forceinline__ void upk2(float& a, float& b, unsigned long long v) {
    asm("mov.b64 {%0, %1}, %2;" : "=f"(a), "=f"(b) : "l"(v));
}
// packed dual-FMA: only reachable via PTX fma.rn.f32x2 (ptxas never auto-fuses)
__device__ __forceinline__ void ffma2(unsigned long long& d, unsigned long long a, unsigned long long b) {
    asm("fma.rn.f32x2 %0, %1, %2, %0;" : "+l"(d) : "l"(a), "l"(b));
}

// ---------------- prep: build effective weights + LUT (high-parallelism) ----------------
__global__ __launch_bounds__(256) void prep_kernel(const float* __restrict__ wDI,
                                                   const float* __restrict__ wNDI) {
    __shared__ float w[FMD * FMD];
    int blk = blockIdx.x;
    int tid = threadIdx.x;
    if (blk < NHEAD * SEGS) {
        int h = blk >> 3, seg = blk & (SEGS - 1);
        const float* src = wNDI + h * FMD * FMD;
        for (int i = tid; i < FMD * FMD; i += 256) w[i] = src[i];
        __syncthreads();
        int t0 = seg * SEGLEN, t1 = min(NBIN, t0 + SEGLEN);
        for (int t = t0 + tid; t < t1; t += 256) {
            // invert upper-triangular index: S(I) = I*73 - I*(I-1)/2
            int I = (int)((147.0f - sqrtf(147.0f * 147.0f - 8.0f * (float)t)) * 0.5f);
            I = max(0, min(72, I));
            while (I > 0 && (I * 73 - (I * (I - 1)) / 2) > t) I--;
            while (I < 72 && ((I + 1) * 73 - ((I + 1) * I) / 2) <= t) I++;
            int J = I + 1 + (t - (I * 73 - (I * (I - 1)) / 2));
            g_wA[t * NHEAD + h] = (w[I * FMD + J] - w[J * FMD + I]) * (1.0f / 16.0f);
            if (h == 0) g_binIJ[t] = (unsigned short)((I << 8) | J);
        }
    } else {
        int h = blk - NHEAD * SEGS;
        const float* src = wDI + h * FMD * FMD;
        for (int i = tid; i < FMD * FMD; i += 256) w[i] = src[i];
        __syncthreads();
        if (tid < FMD) {
            float cs = 0.f, rs = 0.f;
            #pragma unroll 2
            for (int I = 0; I < FMD; I++) {
                cs += w[I * FMD + tid];   // column sum
                rs += w[tid * FMD + I];   // row sum
            }
            g_wDIeff[tid * NHEAD + h] = (cs - rs) * 0.25f;
        }
    }
}

// ---------------- fused: on-the-fly pool + head contraction + full MLP tail ----------------
struct TailS {
    float hN[RB][NHEAD];
    float hD[RB][NHEAD];
    float emb[RB][2 * NEMB];
    float z1[RB][NEMB];
    float z2[RB][20];
};
union SmemU {
    float xe[RB][NW];   // 18944 B  (row stride 1184 B, 16B-aligned)
    TailS t;            // 18688 B
};

__global__ __launch_bounds__(512) void fused_kernel(
    const float* __restrict__ x,
    const float* __restrict__ bDI,   const float* __restrict__ fcDI_w,  const float* __restrict__ fcDI_b,
    const float* __restrict__ bNDI,  const float* __restrict__ fcNDI_w, const float* __restrict__ fcNDI_b,
    const float* __restrict__ fc1_w, const float* __restrict__ fc1_b,
    const float* __restrict__ l1_w,  const float* __restrict__ l1_b,
    const float* __restrict__ l2_w,  const float* __restrict__ l2_b,
    float* __restrict__ out)
{
    __shared__ SmemU u;
    __shared__ float ps[RB][129];          // pooled-NDI chunk (also reused as reduction scratch)
    __shared__ float sus[RB][FMD];         // group sums
    __shared__ unsigned short sIJ[NBIN + 1];

    int tid  = threadIdx.x;
    int row0 = blockIdx.x * RB;
    int hq   = tid & 15;          // head quad: heads 4*hq..4*hq+3
    int half = (tid >> 4) & 1;    // bin-half within chunk
    int rg   = tid >> 5;          // row 0..15

    // stage 0: load LUT + x rows (+eps/2 folded in)
    for (int i = tid; i < NBIN; i += 512) sIJ[i] = g_binIJ[i];
    for (int i = tid; i < RB * NW; i += 512) {
        int r = i / NW, c = i % NW;
        u.xe[r][c] = x[(size_t)(row0 + r) * 300 + c] + 5e-6f;
    }
    __syncthreads();
    // group sums (constant eps offset cancels in DI head since weights sum to 0 there)
    for (int i = tid; i < RB * FMD; i += 512) {
        int r = i / FMD, K = i % FMD;
        float4 v = ((const float4*)u.xe[r])[K];
        sus[r][K] = v.x + v.y + v.z + v.w;
    }

    unsigned long long a01 = 0ull, a23 = 0ull;   // packed f32x2 accumulators
    for (int c0 = 0; c0 < NBIN; c0 += 128) {
        int nb = min(128, NBIN - c0);
        __syncthreads();   // ps reuse barrier (also orders sus/xe on first iter)
        // ---- stage 1: pooled NDI for this chunk (raw 16-pair sums; /16 folded into wA)
        for (int idx = tid; idx < RB * 128; idx += 512) {
            int r = idx >> 7, b = idx & 127;
            float val = 0.f;
            if (b < nb) {
                unsigned ij = sIJ[c0 + b];
                const float4* xs4 = (const float4*)u.xe[r];
                float4 a = xs4[ij >> 8];    // group I (rows)
                float4 bb = xs4[ij & 255];  // group J (cols)
                float av[4] = {a.x, a.y, a.z, a.w};
                float bv[4] = {bb.x, bb.y, bb.z, bb.w};
                float acc = 0.f;
                #pragma unroll
                for (int j = 0; j < 4; j++) {
                    float xj = bv[j];
                    #pragma unroll
                    for (int i = 0; i < 4; i += 2) {
                        // two fractions over a common denominator: 1 rcp per 2 pairs
                        float s0 = av[i]     + xj, d0 = xj - av[i];
                        float s1 = av[i + 1] + xj, d1 = xj - av[i + 1];
                        float num = fmaf(d0, s1, d1 * s0);
                        float den = s0 * s1;
                        float y;
                        asm("rcp.approx.f32 %0, %1;" : "=f"(y) : "f"(den));
                        acc = fmaf(num, y, acc);
                    }
                }
                val = acc;
            }
            ps[r][b] = val;
        }
        __syncthreads();
        // ---- stage 2: contraction, bins split across half-warps, FFMA2 packed
        int bend = min((half + 1) * 64, nb);
        const ulonglong2* wp = (const ulonglong2*)(g_wA + (size_t)c0 * NHEAD) + hq;
        #pragma unroll 4
        for (int b = half * 64; b < bend; b++) {
            ulonglong2 w = wp[(size_t)b * 16];
            unsigned long long pp = pk2(ps[rg][b], ps[rg][b]);
            ffma2(a01, pp, w.x);
            ffma2(a23, pp, w.y);
        }
    }
    __syncthreads();

    // reduce half-accumulators -> hN (scratch aliases ps)
    float (*red)[NHEAD] = (float(*)[NHEAD])ps;
    float acc0, acc1, acc2, acc3;
    upk2(acc0, acc1, a01);
    upk2(acc2, acc3, a23);
    if (half == 1) {
        red[rg][4 * hq + 0] = acc0; red[rg][4 * hq + 1] = acc1;
        red[rg][4 * hq + 2] = acc2; red[rg][4 * hq + 3] = acc3;
    }
    __syncthreads();
    if (half == 0) {
        acc0 += red[rg][4 * hq + 0]; acc1 += red[rg][4 * hq + 1];
        acc2 += red[rg][4 * hq + 2]; acc3 += red[rg][4 * hq + 3];
        u.t.hN[rg][4 * hq + 0] = elu1(acc0 + bNDI[4 * hq + 0]);
        u.t.hN[rg][4 * hq + 1] = elu1(acc1 + bNDI[4 * hq + 1]);
        u.t.hN[rg][4 * hq + 2] = elu1(acc2 + bNDI[4 * hq + 2]);
        u.t.hN[rg][4 * hq + 3] = elu1(acc3 + bNDI[4 * hq + 3]);
    }
    __syncthreads();

    // DI head: h_DI = su . wDIeff  (K split across halves, packed)
    unsigned long long d01 = 0ull, d23 = 0ull;
    #pragma unroll 2
    for (int K = half * 37; K < half * 37 + 37; K++) {
        ulonglong2 w = *(const ulonglong2*)(g_wDIeff + K * NHEAD + 4 * hq);
        unsigned long long pp = pk2(sus[rg][K], sus[rg][K]);
        ffma2(d01, pp, w.x);
        ffma2(d23, pp, w.y);
    }
    float dc0, dc1, dc2, dc3;
    upk2(dc0, dc1, d01);
    upk2(dc2, dc3, d23);
    if (half == 1) {
        red[rg][4 * hq + 0] = dc0; red[rg][4 * hq + 1] = dc1;
        red[rg][4 * hq + 2] = dc2; red[rg][4 * hq + 3] = dc3;
    }
    __syncthreads();
    if (half == 0) {
        dc0 += red[rg][4 * hq + 0]; dc1 += red[rg][4 * hq + 1];
        dc2 += red[rg][4 * hq + 2]; dc3 += red[rg][4 * hq + 3];
        u.t.hD[rg][4 * hq + 0] = elu1(dc0 + bDI[4 * hq + 0]);
        u.t.hD[rg][4 * hq + 1] = elu1(dc1 + bDI[4 * hq + 1]);
        u.t.hD[rg][4 * hq + 2] = elu1(dc2 + bDI[4 * hq + 2]);
        u.t.hD[rg][4 * hq + 3] = elu1(dc3 + bDI[4 * hq + 3]);
    }
    __syncthreads();

    // eDI / eNDI (48 each) -> emb[96]
    for (int idx = tid; idx < RB * NEMB; idx += 512) {
        int r = idx / NEMB, e = idx % NEMB;
        float v = fcDI_b[e], v2 = fcNDI_b[e];
        #pragma unroll 8
        for (int h = 0; h < NHEAD; h++) {
            v  = fmaf(fcDI_w[e * NHEAD + h],  u.t.hD[r][h], v);
            v2 = fmaf(fcNDI_w[e * NHEAD + h], u.t.hN[r][h], v2);
        }
        u.t.emb[r][e]        = elu1(v);
        u.t.emb[r][NEMB + e] = elu1(v2);
    }
    __syncthreads();

    // fc1: 96 -> 48
    for (int idx = tid; idx < RB * NEMB; idx += 512) {
        int r = idx / NEMB, o = idx % NEMB;
        float v = fc1_b[o];
        #pragma unroll 8
        for (int c = 0; c < 2 * NEMB; c++) v = fmaf(fc1_w[o * 2 * NEMB + c], u.t.emb[r][c], v);
        u.t.z1[r][o] = elu1(v);
    }
    __syncthreads();

    // l1: 48 -> 20
    for (int idx = tid; idx < RB * 20; idx += 512) {
        int r = idx / 20, o = idx % 20;
        float v = l1_b[o];
        #pragma unroll 8
        for (int c = 0; c < NEMB; c++) v = fmaf(l1_w[o * NEMB + c], u.t.z1[r][c], v);
        u.t.z2[r][o] = elu1(v);
    }
    __syncthreads();

    // l2: 20 -> 1, sigmoid
    if (tid < RB) {
        float v = l2_b[0];
        #pragma unroll
        for (int c = 0; c < 20; c++) v = fmaf(l2_w[c], u.t.z2[tid][c], v);
        out[row0 + tid] = 1.0f / (1.0f + expf(-v));
    }
}

extern "C" void kernel_launch(void* const* d_in, const int* in_sizes, int n_in,
                              void* d_out, int out_size) {
    const float* x       = (const float*)d_in[0];
    const float* wDI     = (const float*)d_in[1];
    const float* bDI     = (const float*)d_in[2];
    const float* fcDI_w  = (const float*)d_in[3];
    const float* fcDI_b  = (const float*)d_in[4];
    const float* wNDI    = (const float*)d_in[5];
    const float* bNDI    = (const float*)d_in[6];
    const float* fcNDI_w = (const float*)d_in[7];
    const float* fcNDI_b = (const float*)d_in[8];
    const float* fc1_w   = (const float*)d_in[9];
    const float* fc1_b   = (const float*)d_in[10];
    const float* l1_w    = (const float*)d_in[11];
    const float* l1_b    = (const float*)d_in[12];
    const float* l2_w    = (const float*)d_in[13];
    const float* l2_b    = (const float*)d_in[14];
    float* out = (float*)d_out;

    int B = in_sizes[0] / 300;   // 2048

    prep_kernel<<<NHEAD * SEGS + NHEAD, 256>>>(wDI, wNDI);
    fused_kernel<<<B / RB, 512>>>(x, bDI, fcDI_w, fcDI_b, bNDI, fcNDI_w, fcNDI_b,
                                  fc1_w, fc1_b, l1_w, l1_b, l2_w, l2_b, out);
}

// round 8
// speedup vs baseline: 3.3800x; 2.3213x over previous
#include <cuda_runtime.h>
#include <math.h>

#define NW    296
#define FMD   74
#define NBIN  2701          // 74*73/2
#define NBINP 2816          // 22 * 128 (padded; pad weights stay zero)
#define NCHUNK 22
#define NHEAD 64
#define NEMB  48
#define RB    8             // rows per block
#define SEGS  8
#define SEGLEN ((NBIN + SEGS - 1) / SEGS)   // 338

// __device__ scratch (zero-initialized at module load; pads never written)
__device__ float g_wA[NBINP * NHEAD];       // (wNDI[h,I,J]-wNDI[h,J,I])/16, bin-major
__device__ float g_wDIeff[FMD * NHEAD];     // (colsum-rowsum)/4, K-major
__device__ unsigned short g_binIJ[NBIN];    // (I<<8)|J

__device__ __forceinline__ float elu1(float v) { return v > 0.f ? v : expm1f(v); }

__device__ __forceinline__ unsigned long long pk2(float a, float b) {
    unsigned long long r;
    asm("mov.b64 %0, {%1, %2};" : "=l"(r) : "f"(a), "f"(b));
    return r;
}
__device__ __forceinline__ void upk2(float& a, float& b, unsigned long long v) {
    asm("mov.b64 {%0, %1}, %2;" : "=f"(a), "=f"(b) : "l"(v));
}
// packed dual-FMA: only reachable via PTX fma.rn.f32x2
__device__ __forceinline__ void ffma2(unsigned long long& d, unsigned long long a, unsigned long long b) {
    asm("fma.rn.f32x2 %0, %1, %2, %0;" : "+l"(d) : "l"(a), "l"(b));
}

// ---------------- prep: build effective weights + LUT ----------------
__global__ __launch_bounds__(256) void prep_kernel(const float* __restrict__ wDI,
                                                   const float* __restrict__ wNDI) {
    __shared__ float w[FMD * FMD];
    int blk = blockIdx.x;
    int tid = threadIdx.x;
    if (blk < NHEAD * SEGS) {
        int h = blk >> 3, seg = blk & (SEGS - 1);
        const float* src = wNDI + h * FMD * FMD;
        for (int i = tid; i < FMD * FMD; i += 256) w[i] = src[i];
        __syncthreads();
        int t0 = seg * SEGLEN, t1 = min(NBIN, t0 + SEGLEN);
        for (int t = t0 + tid; t < t1; t += 256) {
            int I = (int)((147.0f - sqrtf(147.0f * 147.0f - 8.0f * (float)t)) * 0.5f);
            I = max(0, min(72, I));
            while (I > 0 && (I * 73 - (I * (I - 1)) / 2) > t) I--;
            while (I < 72 && ((I + 1) * 73 - ((I + 1) * I) / 2) <= t) I++;
            int J = I + 1 + (t - (I * 73 - (I * (I - 1)) / 2));
            g_wA[t * NHEAD + h] = (w[I * FMD + J] - w[J * FMD + I]) * (1.0f / 16.0f);
            if (h == 0) g_binIJ[t] = (unsigned short)((I << 8) | J);
        }
    } else {
        int h = blk - NHEAD * SEGS;
        const float* src = wDI + h * FMD * FMD;
        for (int i = tid; i < FMD * FMD; i += 256) w[i] = src[i];
        __syncthreads();
        if (tid < FMD) {
            float cs = 0.f, rs = 0.f;
            #pragma unroll 2
            for (int I = 0; I < FMD; I++) {
                cs += w[I * FMD + tid];
                rs += w[tid * FMD + I];
            }
            g_wDIeff[tid * NHEAD + h] = (cs - rs) * 0.25f;
        }
    }
}

// ---------------- fused: on-the-fly pool + contraction + MLP tail ----------------
struct TailS {
    float hN[RB][NHEAD];
    float hD[RB][NHEAD];
    float emb[RB][2 * NEMB];
    float z1[RB][NEMB];
    float z2[RB][20];
};
union BigU {
    struct { float xe[RB][NW]; float ps[2][RB][128]; } a;  // 9472 + 8192 = 17664 B
    float red[8][RB][NHEAD];                               // 16384 B (slot reduction)
};

__global__ __launch_bounds__(512, 2) void fused_kernel(
    const float* __restrict__ x,
    const float* __restrict__ bDI,   const float* __restrict__ fcDI_w,  const float* __restrict__ fcDI_b,
    const float* __restrict__ bNDI,  const float* __restrict__ fcNDI_w, const float* __restrict__ fcNDI_b,
    const float* __restrict__ fc1_w, const float* __restrict__ fc1_b,
    const float* __restrict__ l1_w,  const float* __restrict__ l1_b,
    const float* __restrict__ l2_w,  const float* __restrict__ l2_b,
    float* __restrict__ out)
{
    __shared__ BigU u;
    __shared__ TailS t;
    __shared__ float sus[RB][FMD];
    __shared__ unsigned short sIJ[NBINP];

    int tid  = threadIdx.x;
    int row0 = blockIdx.x * RB;

    // contraction mapping: 16 head-quads x 8 bin-slots x 4 row-groups (2 rows each)
    int hq   = tid & 15;
    int slot = (tid >> 4) & 7;
    int rgrp = tid >> 7;          // 0..3
    int r0   = 2 * rgrp, r1 = r0 + 1;

    // stage 0: LUT (zero-padded) + x rows (+eps/2 folded in)
    for (int i = tid; i < NBINP; i += 512) sIJ[i] = (i < NBIN) ? g_binIJ[i] : (unsigned short)0;
    for (int i = tid; i < RB * NW; i += 512) {
        int r = i / NW, c = i % NW;
        u.a.xe[r][c] = x[(size_t)(row0 + r) * 300 + c] + 5e-6f;
    }
    __syncthreads();
    // group sums — RB*FMD = 592 > 512, MUST be a strided loop (R6 bug was a guard here)
    for (int i = tid; i < RB * FMD; i += 512) {
        int r = i / FMD, K = i % FMD;
        float4 v = ((const float4*)u.a.xe[r])[K];
        sus[r][K] = v.x + v.y + v.z + v.w;
    }

    // ---- pooled-NDI producer for one 128-bin chunk into ps[buf]
    #define STAGE1(C0, BUF)                                                         \
    {                                                                               \
        _Pragma("unroll")                                                           \
        for (int it = 0; it < 2; it++) {                                            \
            int idx = tid + it * 512;                                               \
            int r = idx >> 7, b = idx & 127;                                        \
            unsigned ij = sIJ[(C0) + b];                                            \
            const float4* xs4 = (const float4*)u.a.xe[r];                           \
            float4 ga = xs4[ij >> 8];                                               \
            float4 gb = xs4[ij & 255];                                              \
            float av[4] = {ga.x, ga.y, ga.z, ga.w};                                 \
            float bv[4] = {gb.x, gb.y, gb.z, gb.w};                                 \
            float acc = 0.f;                                                        \
            _Pragma("unroll")                                                       \
            for (int j = 0; j < 4; j++) {                                           \
                float xj = bv[j];                                                   \
                _Pragma("unroll")                                                   \
                for (int i = 0; i < 4; i += 2) {                                    \
                    float s0 = av[i] + xj,     d0 = xj - av[i];                     \
                    float s1 = av[i + 1] + xj, d1 = xj - av[i + 1];                 \
                    float num = fmaf(d0, s1, d1 * s0);                              \
                    float den = s0 * s1;                                            \
                    float y;                                                        \
                    asm("rcp.approx.f32 %0, %1;" : "=f"(y) : "f"(den));             \
                    acc = fmaf(num, y, acc);                                        \
                }                                                                   \
            }                                                                       \
            u.a.ps[BUF][r][b] = acc;                                                \
        }                                                                           \
    }

    unsigned long long a00 = 0ull, a01 = 0ull, a10 = 0ull, a11 = 0ull;

    STAGE1(0, 0);
    __syncthreads();
    for (int c = 0; c < NCHUNK; c++) {
        int buf = c & 1;
        int c0 = c << 7;
        if (c < NCHUNK - 1) STAGE1(c0 + 128, buf ^ 1);
        // consumer: 16 bins per thread, each w quad feeds 2 rows (4 FFMA2)
        const float* wbase = g_wA + (size_t)c0 * NHEAD + 4 * hq;
        #pragma unroll 4
        for (int i = 0; i < 16; i++) {
            int b = slot + 8 * i;
            ulonglong2 w = *(const ulonglong2*)(wbase + (size_t)b * NHEAD);
            float p0 = u.a.ps[buf][r0][b];
            float p1 = u.a.ps[buf][r1][b];
            unsigned long long pp0 = pk2(p0, p0);
            unsigned long long pp1 = pk2(p1, p1);
            ffma2(a00, pp0, w.x); ffma2(a01, pp0, w.y);
            ffma2(a10, pp1, w.x); ffma2(a11, pp1, w.y);
        }
        __syncthreads();
    }

    // ---- reduce 8 bin-slots via smem (red aliases xe/ps; both dead now)
    {
        float v0, v1, v2, v3;
        upk2(v0, v1, a00); upk2(v2, v3, a01);
        u.red[slot][r0][4 * hq + 0] = v0; u.red[slot][r0][4 * hq + 1] = v1;
        u.red[slot][r0][4 * hq + 2] = v2; u.red[slot][r0][4 * hq + 3] = v3;
        upk2(v0, v1, a10); upk2(v2, v3, a11);
        u.red[slot][r1][4 * hq + 0] = v0; u.red[slot][r1][4 * hq + 1] = v1;
        u.red[slot][r1][4 * hq + 2] = v2; u.red[slot][r1][4 * hq + 3] = v3;
    }
    __syncthreads();

    // one thread per (row, head): NDI reduce + bias + elu; DI head full dot
    {
        int r = tid >> 6, h = tid & 63;
        float s = 0.f;
        #pragma unroll
        for (int s8 = 0; s8 < 8; s8++) s += u.red[s8][r][h];
        t.hN[r][h] = elu1(s + bNDI[h]);

        float d = 0.f;
        #pragma unroll 2
        for (int K = 0; K < FMD; K++)
            d = fmaf(sus[r][K], g_wDIeff[K * NHEAD + h], d);
        t.hD[r][h] = elu1(d + bDI[h]);
    }
    __syncthreads();

    // eDI / eNDI (48 each) -> emb[96]
    if (tid < RB * NEMB) {
        int r = tid / NEMB, e = tid % NEMB;
        float v = fcDI_b[e], v2 = fcNDI_b[e];
        #pragma unroll 8
        for (int h = 0; h < NHEAD; h++) {
            v  = fmaf(fcDI_w[e * NHEAD + h],  t.hD[r][h], v);
            v2 = fmaf(fcNDI_w[e * NHEAD + h], t.hN[r][h], v2);
        }
        t.emb[r][e]        = elu1(v);
        t.emb[r][NEMB + e] = elu1(v2);
    }
    __syncthreads();

    // fc1: 96 -> 48
    if (tid < RB * NEMB) {
        int r = tid / NEMB, o = tid % NEMB;
        float v = fc1_b[o];
        #pragma unroll 8
        for (int c = 0; c < 2 * NEMB; c++) v = fmaf(fc1_w[o * 2 * NEMB + c], t.emb[r][c], v);
        t.z1[r][o] = elu1(v);
    }
    __syncthreads();

    // l1: 48 -> 20
    if (tid < RB * 20) {
        int r = tid / 20, o = tid % 20;
        float v = l1_b[o];
        #pragma unroll 8
        for (int c = 0; c < NEMB; c++) v = fmaf(l1_w[o * NEMB + c], t.z1[r][c], v);
        t.z2[r][o] = elu1(v);
    }
    __syncthreads();

    // l2: 20 -> 1, sigmoid
    if (tid < RB) {
        float v = l2_b[0];
        #pragma unroll
        for (int c = 0; c < 20; c++) v = fmaf(l2_w[c], t.z2[tid][c], v);
        out[row0 + tid] = 1.0f / (1.0f + expf(-v));
    }
}

extern "C" void kernel_launch(void* const* d_in, const int* in_sizes, int n_in,
                              void* d_out, int out_size) {
    const float* x       = (const float*)d_in[0];
    const float* wDI     = (const float*)d_in[1];
    const float* bDI     = (const float*)d_in[2];
    const float* fcDI_w  = (const float*)d_in[3];
    const float* fcDI_b  = (const float*)d_in[4];
    const float* wNDI    = (const float*)d_in[5];
    const float* bNDI    = (const float*)d_in[6];
    const float* fcNDI_w = (const float*)d_in[7];
    const float* fcNDI_b = (const float*)d_in[8];
    const float* fc1_w   = (const float*)d_in[9];
    const float* fc1_b   = (const float*)d_in[10];
    const float* l1_w    = (const float*)d_in[11];
    const float* l1_b    = (const float*)d_in[12];
    const float* l2_w    = (const float*)d_in[13];
    const float* l2_b    = (const float*)d_in[14];
    float* out = (float*)d_out;

    int B = in_sizes[0] / 300;   // 2048

    prep_kernel<<<NHEAD * SEGS + NHEAD, 256>>>(wDI, wNDI);
    fused_kernel<<<B / RB, 512>>>(x, bDI, fcDI_w, fcDI_b, bNDI, fcNDI_w, fcNDI_b,
                                  fc1_w, fc1_b, l1_w, l1_b, l2_w, l2_b, out);
}

// round 10
// speedup vs baseline: 3.6267x; 1.0730x over previous
#include <cuda_runtime.h>
#include <math.h>

#define NW    296
#define FMD   74
#define NBIN  2701          // 74*73/2
#define NBINP 2816          // 22 * 128 (padded; pad weights stay zero)
#define NCHUNK 22
#define NHEAD 64
#define NEMB  48
#define RB    8             // rows per block
#define SEGS  8
#define SEGLEN ((NBIN + SEGS - 1) / SEGS)   // 338

// __device__ scratch (zero-initialized at module load; pads never written)
__device__ float g_wA[NBINP * NHEAD];       // (wNDI[h,I,J]-wNDI[h,J,I])/16, bin-major
__device__ float g_wDIeff[FMD * NHEAD];     // (colsum-rowsum)/4, K-major
__device__ unsigned short g_binIJ[NBIN];    // (I<<8)|J

__device__ __forceinline__ float elu1(float v) { return v > 0.f ? v : expm1f(v); }

__device__ __forceinline__ unsigned long long pk2(float a, float b) {
    unsigned long long r;
    asm("mov.b64 %0, {%1, %2};" : "=l"(r) : "f"(a), "f"(b));
    return r;
}
__device__ __forceinline__ void upk2(float& a, float& b, unsigned long long v) {
    asm("mov.b64 {%0, %1}, %2;" : "=f"(a), "=f"(b) : "l"(v));
}
// packed dual-FMA: only reachable via PTX fma.rn.f32x2
__device__ __forceinline__ void ffma2(unsigned long long& d, unsigned long long a, unsigned long long b) {
    asm("fma.rn.f32x2 %0, %1, %2, %0;" : "+l"(d) : "l"(a), "l"(b));
}

// ---------------- prep: build effective weights + LUT ----------------
__global__ __launch_bounds__(256) void prep_kernel(const float* __restrict__ wDI,
                                                   const float* __restrict__ wNDI) {
    __shared__ float w[FMD * FMD];
    int blk = blockIdx.x;
    int tid = threadIdx.x;
    if (blk < NHEAD * SEGS) {
        int h = blk >> 3, seg = blk & (SEGS - 1);
        const float* src = wNDI + h * FMD * FMD;
        for (int i = tid; i < FMD * FMD; i += 256) w[i] = src[i];
        __syncthreads();
        int t0 = seg * SEGLEN, t1 = min(NBIN, t0 + SEGLEN);
        for (int t = t0 + tid; t < t1; t += 256) {
            int I = (int)((147.0f - sqrtf(147.0f * 147.0f - 8.0f * (float)t)) * 0.5f);
            I = max(0, min(72, I));
            while (I > 0 && (I * 73 - (I * (I - 1)) / 2) > t) I--;
            while (I < 72 && ((I + 1) * 73 - ((I + 1) * I) / 2) <= t) I++;
            int J = I + 1 + (t - (I * 73 - (I * (I - 1)) / 2));
            g_wA[t * NHEAD + h] = (w[I * FMD + J] - w[J * FMD + I]) * (1.0f / 16.0f);
            if (h == 0) g_binIJ[t] = (unsigned short)((I << 8) | J);
        }
    } else {
        int h = blk - NHEAD * SEGS;
        const float* src = wDI + h * FMD * FMD;
        for (int i = tid; i < FMD * FMD; i += 256) w[i] = src[i];
        __syncthreads();
        if (tid < FMD) {
            float cs = 0.f, rs = 0.f;
            #pragma unroll 2
            for (int I = 0; I < FMD; I++) {
                cs += w[I * FMD + tid];
                rs += w[tid * FMD + I];
            }
            g_wDIeff[tid * NHEAD + h] = (cs - rs) * 0.25f;
        }
    }
}

// ---------------- fused: on-the-fly pool + contraction + MLP tail ----------------
struct TailS {
    float hN[RB][NHEAD];
    float hD[RB][NHEAD];
    float emb[RB][2 * NEMB];
    float z1[RB][NEMB];
    float z2[RB][20];
};
union BigU {
    struct {
        float xe[RB][NW];          // 9472 B
        float ps2[2][128][RB];     // 8192 B  (bin-major, row minor: broadcast-friendly)
    } a;
    unsigned long long red[8][RB][32];   // 16384 B slot-reduction (slot, row, head-pair)
    float redf[8][RB][NHEAD];            // float view of the same
};

__global__ __launch_bounds__(512, 2) void fused_kernel(
    const float* __restrict__ x,
    const float* __restrict__ bDI,   const float* __restrict__ fcDI_w,  const float* __restrict__ fcDI_b,
    const float* __restrict__ bNDI,  const float* __restrict__ fcNDI_w, const float* __restrict__ fcNDI_b,
    const float* __restrict__ fc1_w, const float* __restrict__ fc1_b,
    const float* __restrict__ l1_w,  const float* __restrict__ l1_b,
    const float* __restrict__ l2_w,  const float* __restrict__ l2_b,
    float* __restrict__ out)
{
    __shared__ BigU u;
    __shared__ TailS t;
    __shared__ float sus[RB][FMD];
    __shared__ unsigned short sIJ[NBINP];

    int tid  = threadIdx.x;
    int row0 = blockIdx.x * RB;

    // consumer mapping: 32 head-pairs x 8 bin-slots x 2 row-groups (4 rows each)
    int hp   = tid & 31;          // heads 2hp, 2hp+1
    int slot = (tid >> 5) & 7;    // bin slot
    int rgrp = tid >> 8;          // 0..1, rows 4*rgrp..4*rgrp+3

    // stage 0: LUT (zero-padded) + x rows (+eps/2 folded in)
    for (int i = tid; i < NBINP; i += 512) sIJ[i] = (i < NBIN) ? g_binIJ[i] : (unsigned short)0;
    for (int i = tid; i < RB * NW; i += 512) {
        int r = i / NW, c = i % NW;
        u.a.xe[r][c] = x[(size_t)(row0 + r) * 300 + c] + 5e-6f;
    }
    __syncthreads();
    // group sums — RB*FMD = 592 > 512: strided loop required
    for (int i = tid; i < RB * FMD; i += 512) {
        int r = i / FMD, K = i % FMD;
        float4 v = ((const float4*)u.a.xe[r])[K];
        sus[r][K] = v.x + v.y + v.z + v.w;
    }

    // ---- pooled-NDI producer: one 128-bin chunk -> ps2[buf][b][r]
    // 4 fractions share one denominator: 4 rcp per bin (was 8)
    #define STAGE1(C0, BUF)                                                         \
    {                                                                               \
        _Pragma("unroll")                                                           \
        for (int it = 0; it < 2; it++) {                                            \
            int idx = tid + it * 512;                                               \
            int r = idx & 7, b = idx >> 3;                                          \
            unsigned ij = sIJ[(C0) + b];                                            \
            const float4* xs4 = (const float4*)u.a.xe[r];                           \
            float4 ga = xs4[ij >> 8];                                               \
            float4 gb = xs4[ij & 255];                                              \
            float av[4] = {ga.x, ga.y, ga.z, ga.w};                                 \
            float bv[4] = {gb.x, gb.y, gb.z, gb.w};                                 \
            float acc = 0.f;                                                        \
            _Pragma("unroll")                                                       \
            for (int j = 0; j < 4; j++) {                                           \
                float xj = bv[j];                                                   \
                float s0 = av[0] + xj, d0 = xj - av[0];                             \
                float s1 = av[1] + xj, d1 = xj - av[1];                             \
                float s2 = av[2] + xj, d2 = xj - av[2];                             \
                float s3 = av[3] + xj, d3 = xj - av[3];                             \
                float t01 = s0 * s1, t23 = s2 * s3;                                 \
                float n01 = fmaf(d0, s1, d1 * s0);                                  \
                float n23 = fmaf(d2, s3, d3 * s2);                                  \
                float num = fmaf(n01, t23, n23 * t01);                              \
                float den = t01 * t23;                                              \
                float y;                                                            \
                asm("rcp.approx.f32 %0, %1;" : "=f"(y) : "f"(den));                 \
                acc = fmaf(num, y, acc);                                            \
            }                                                                       \
            u.a.ps2[BUF][b][r] = acc;                                               \
        }                                                                           \
    }

    unsigned long long acc0 = 0ull, acc1 = 0ull, acc2 = 0ull, acc3 = 0ull;

    STAGE1(0, 0);
    __syncthreads();
    for (int c = 0; c < NCHUNK; c++) {
        int buf = c & 1;
        int c0 = c << 7;
        if (c < NCHUNK - 1) STAGE1(c0 + 128, buf ^ 1);
        // consumer: 16 bins/thread; each 8B w load feeds 4 rows (4 FFMA2)
        const float* wbase = g_wA + (size_t)c0 * NHEAD + 2 * hp;
        const float4* pbase = (const float4*)u.a.ps2[buf] + rgrp;   // ps2[b] as float4[2]
        #pragma unroll 4
        for (int i = 0; i < 16; i++) {
            int b = slot + 8 * i;
            unsigned long long w = *(const unsigned long long*)(wbase + (size_t)b * NHEAD);
            float4 p = pbase[b * 2];
            ffma2(acc0, pk2(p.x, p.x), w);
            ffma2(acc1, pk2(p.y, p.y), w);
            ffma2(acc2, pk2(p.z, p.z), w);
            ffma2(acc3, pk2(p.w, p.w), w);
        }
        __syncthreads();
    }

    // ---- reduce 8 bin-slots via aliased smem (xe/ps dead now)
    {
        int r0 = 4 * rgrp;
        u.red[slot][r0 + 0][hp] = acc0;
        u.red[slot][r0 + 1][hp] = acc1;
        u.red[slot][r0 + 2][hp] = acc2;
        u.red[slot][r0 + 3][hp] = acc3;
    }
    __syncthreads();

    // one thread per (row, head): NDI reduce + bias + elu; DI head full dot
    {
        int r = tid >> 6, h = tid & 63;
        float s = 0.f;
        #pragma unroll
        for (int s8 = 0; s8 < 8; s8++) s += u.redf[s8][r][h];
        t.hN[r][h] = elu1(s + bNDI[h]);

        float d = 0.f;
        #pragma unroll 2
        for (int K = 0; K < FMD; K++)
            d = fmaf(sus[r][K], g_wDIeff[K * NHEAD + h], d);
        t.hD[r][h] = elu1(d + bDI[h]);
    }
    __syncthreads();

    // eDI / eNDI (48 each) -> emb[96]
    if (tid < RB * NEMB) {
        int r = tid / NEMB, e = tid % NEMB;
        float v = fcDI_b[e], v2 = fcNDI_b[e];
        #pragma unroll 8
        for (int h = 0; h < NHEAD; h++) {
            v  = fmaf(fcDI_w[e * NHEAD + h],  t.hD[r][h], v);
            v2 = fmaf(fcNDI_w[e * NHEAD + h], t.hN[r][h], v2);
        }
        t.emb[r][e]        = elu1(v);
        t.emb[r][NEMB + e] = elu1(v2);
    }
    __syncthreads();

    // fc1: 96 -> 48
    if (tid < RB * NEMB) {
        int r = tid / NEMB, o = tid % NEMB;
        float v = fc1_b[o];
        #pragma unroll 8
        for (int c = 0; c < 2 * NEMB; c++) v = fmaf(fc1_w[o * 2 * NEMB + c], t.emb[r][c], v);
        t.z1[r][o] = elu1(v);
    }
    __syncthreads();

    // l1: 48 -> 20
    if (tid < RB * 20) {
        int r = tid / 20, o = tid % 20;
        float v = l1_b[o];
        #pragma unroll 8
        for (int c = 0; c < NEMB; c++) v = fmaf(l1_w[o * NEMB + c], t.z1[r][c], v);
        t.z2[r][o] = elu1(v);
    }
    __syncthreads();

    // l2: 20 -> 1, sigmoid
    if (tid < RB) {
        float v = l2_b[0];
        #pragma unroll
        for (int c = 0; c < 20; c++) v = fmaf(l2_w[c], t.z2[tid][c], v);
        out[row0 + tid] = 1.0f / (1.0f + expf(-v));
    }
}

extern "C" void kernel_launch(void* const* d_in, const int* in_sizes, int n_in,
                              void* d_out, int out_size) {
    const float* x       = (const float*)d_in[0];
    const float* wDI     = (const float*)d_in[1];
    const float* bDI     = (const float*)d_in[2];
    const float* fcDI_w  = (const float*)d_in[3];
    const float* fcDI_b  = (const float*)d_in[4];
    const float* wNDI    = (const float*)d_in[5];
    const float* bNDI    = (const float*)d_in[6];
    const float* fcNDI_w = (const float*)d_in[7];
    const float* fcNDI_b = (const float*)d_in[8];
    const float* fc1_w   = (const float*)d_in[9];
    const float* fc1_b   = (const float*)d_in[10];
    const float* l1_w    = (const float*)d_in[11];
    const float* l1_b    = (const float*)d_in[12];
    const float* l2_w    = (const float*)d_in[13];
    const float* l2_b    = (const float*)d_in[14];
    float* out = (float*)d_out;

    int B = in_sizes[0] / 300;   // 2048

    prep_kernel<<<NHEAD * SEGS + NHEAD, 256>>>(wDI, wNDI);
    fused_kernel<<<B / RB, 512>>>(x, bDI, fcDI_w, fcDI_b, bNDI, fcNDI_w, fcNDI_b,
                                  fc1_w, fc1_b, l1_w, l1_b, l2_w, l2_b, out);
}